// round 12
// baseline (speedup 1.0000x reference)
#include <cuda_runtime.h>
#include <cuda_bf16.h>
#include <cstdint>

#define BB 8
#define NN 8192
#define DD 256
#define HH 8
#define MM 64
#define ROWS (BB*NN)

__device__ __nv_bfloat16 g_xh[(size_t)ROWS*DD];
__device__ __nv_bfloat16 g_xl[(size_t)ROWS*DD];
__device__ __nv_bfloat16 g_wh[768*256];
__device__ __nv_bfloat16 g_wl[768*256];
__device__ __nv_bfloat16 g_woh[256*256];
__device__ __nv_bfloat16 g_wol[256*256];
__device__ unsigned short g_qh[(size_t)ROWS*DD];
__device__ unsigned short g_ql[(size_t)ROWS*DD];
__device__ unsigned short g_kh[(size_t)ROWS*DD];
__device__ unsigned short g_kl[(size_t)ROWS*DD];
__device__ unsigned short g_vth[(size_t)BB*HH*32*NN];
__device__ unsigned short g_vtl[(size_t)BB*HH*32*NN];
__device__ unsigned short g_ath[(size_t)ROWS*DD];
__device__ unsigned short g_atl[(size_t)ROWS*DD];
__device__ unsigned short g_ph[2048], g_pl[2048];
__device__ unsigned short g_cth[64*2048], g_ctl[64*2048];
__device__ float g_ctx[BB*HH*MM*32];
__device__ float g_ksum[BB*HH*MM];
__device__ int g_cnt[64];
__device__ unsigned char g_msk[ROWS];
__device__ unsigned int g_maxe[BB*DD];
__device__ float g_sump[BB*DD];

__device__ __forceinline__ unsigned int fenc(float f){
  unsigned int u=__float_as_uint(f);
  return (u&0x80000000u)?~u:(u|0x80000000u);
}
__device__ __forceinline__ float fdec(unsigned int u){
  unsigned int b=(u&0x80000000u)?(u&0x7fffffffu):~u;
  return __uint_as_float(b);
}
__device__ __forceinline__ void f2hl(float v, unsigned short&h, unsigned short&l){
  __nv_bfloat16 hb=__float2bfloat16(v);
  __nv_bfloat16 lb=__float2bfloat16(v-__bfloat162float(hb));
  h=*(unsigned short*)&hb; l=*(unsigned short*)&lb;
}
__device__ __forceinline__ uint32_t pk(unsigned short a, unsigned short b){
  return (uint32_t)a | ((uint32_t)b<<16);
}
__device__ __forceinline__ void mma16816(float* d, const uint32_t* a,
                                         uint32_t b0, uint32_t b1){
  asm volatile(
    "mma.sync.aligned.m16n8k16.row.col.f32.bf16.bf16.f32 "
    "{%0,%1,%2,%3}, {%4,%5,%6,%7}, {%8,%9}, {%0,%1,%2,%3};"
    : "+f"(d[0]),"+f"(d[1]),"+f"(d[2]),"+f"(d[3])
    : "r"(a[0]),"r"(a[1]),"r"(a[2]),"r"(a[3]),"r"(b0),"r"(b1));
}
__device__ __forceinline__ void ldm4(uint32_t* r, uint32_t addr){
  asm volatile("ldmatrix.sync.aligned.m8n8.x4.shared.b16 {%0,%1,%2,%3}, [%4];"
    : "=r"(r[0]),"=r"(r[1]),"=r"(r[2]),"=r"(r[3]) : "r"(addr));
}
__device__ __forceinline__ uint32_t smem_u32(const void* p){
  uint32_t a;
  asm("{ .reg .u64 t; cvta.to.shared.u64 t, %1; cvt.u32.u64 %0, t; }":"=r"(a):"l"(p));
  return a;
}
__device__ __forceinline__ void cpa16(uint32_t dst, const void* src){
  asm volatile("cp.async.cg.shared.global [%0], [%1], 16;"::"r"(dst),"l"(src):"memory");
}
__device__ __forceinline__ void cpa_commit(){
  asm volatile("cp.async.commit_group;":::"memory");
}
template<int N> __device__ __forceinline__ void cpa_wait(){
  asm volatile("cp.async.wait_group %0;"::"n"(N):"memory");
}

// ---- K0: zero + mask + weight/proj preps ----
__global__ void k_zero(const float* __restrict__ Wq, const float* __restrict__ Wk,
                       const float* __restrict__ Wv, const float* __restrict__ Wo,
                       const float* __restrict__ proj, const void* __restrict__ mp){
  int n=blockIdx.x, k=threadIdx.x;
  if(n<768){
    const float* W=(n<256)?Wq:((n<512)?Wk:Wv);
    float v=W[k*256+(n&255)];
    __nv_bfloat16 h=__float2bfloat16(v);
    g_wh[n*256+k]=h;
    g_wl[n*256+k]=__float2bfloat16(v-__bfloat162float(h));
  }else{
    int c=n-768;
    float v=Wo[k*256+c];
    __nv_bfloat16 h=__float2bfloat16(v);
    g_woh[c*256+k]=h;
    g_wol[c*256+k]=__float2bfloat16(v-__bfloat162float(h));
  }
  int i=n*256+k;
  if(n<8) f2hl(proj[i], g_ph[i], g_pl[i]);
  if(n<256){
    unsigned int w=*(const unsigned int*)mp;
    int v;
    if(w==0x3F800000u)      v=((const float*)mp)[i]!=0.f;
    else if(w==1u)          v=((const int*)mp)[i]!=0;
    else                    v=((const unsigned char*)mp)[i]!=0;
    g_msk[i]=(unsigned char)v;
  }
  if(i<BB*HH*MM*32) g_ctx[i]=0.f;
  if(i<BB*HH*MM)    g_ksum[i]=0.f;
  if(i<64)          g_cnt[i]=0;
  if(i<BB*DD){ g_maxe[i]=0u; g_sump[i]=0.f; }
}

// ---- K1: LayerNorm1 -> bf16 hi/lo ----
__global__ void __launch_bounds__(256) k_ln1(const float* __restrict__ x,
                                             const float* __restrict__ g,
                                             const float* __restrict__ b){
  int lane=threadIdx.x&31, w=threadIdx.x>>5;
  size_t row=(size_t)blockIdx.x*8+w;
  const float4* xr=(const float4*)(x+row*DD);
  float4 a0=xr[lane*2], a1=xr[lane*2+1];
  float s=a0.x+a0.y+a0.z+a0.w+a1.x+a1.y+a1.z+a1.w;
  #pragma unroll
  for(int o=16;o;o>>=1) s+=__shfl_xor_sync(0xffffffffu,s,o);
  float mu=s*(1.f/DD);
  float dv[8]={a0.x-mu,a0.y-mu,a0.z-mu,a0.w-mu,a1.x-mu,a1.y-mu,a1.z-mu,a1.w-mu};
  float q=0.f;
  #pragma unroll
  for(int j=0;j<8;j++) q+=dv[j]*dv[j];
  #pragma unroll
  for(int o=16;o;o>>=1) q+=__shfl_xor_sync(0xffffffffu,q,o);
  float rs=rsqrtf(q*(1.f/DD)+1e-5f);
  float4 g0=((const float4*)g)[lane*2], g1v=((const float4*)g)[lane*2+1];
  float4 b0=((const float4*)b)[lane*2], b1v=((const float4*)b)[lane*2+1];
  float gv[8]={g0.x,g0.y,g0.z,g0.w,g1v.x,g1v.y,g1v.z,g1v.w};
  float bvv[8]={b0.x,b0.y,b0.z,b0.w,b1v.x,b1v.y,b1v.z,b1v.w};
  uint4 hv, lv;
  unsigned short* hp=(unsigned short*)&hv;
  unsigned short* lp=(unsigned short*)&lv;
  #pragma unroll
  for(int j=0;j<8;j++) f2hl(dv[j]*rs*gv[j]+bvv[j], hp[j], lp[j]);
  *(uint4*)(g_xh+row*256+lane*8)=hv;
  *(uint4*)(g_xl+row*256+lane*8)=lv;
}

// ---- K2: QKV GEMM (unchanged from R11) ----
#define QKV_SMEM3 (81920)
__global__ void __launch_bounds__(256,2) k_qkv_mma(
    const float* __restrict__ bq, const float* __restrict__ bk,
    const float* __restrict__ bv){
  extern __shared__ __align__(128) char dsm[];
  __shared__ int anyv;
  int tid=threadIdx.x, lane=tid&31, warp=tid>>5;
  int nt=blockIdx.x, R0=blockIdx.y*128;
  int sec=nt>>1, n0=nt*128;
  if(tid==0) anyv=0;
  __syncthreads();
  if(tid<128 && g_msk[R0+tid]) anyv=1;
  __syncthreads();
  if(sec!=1 && !anyv){
    if(sec==2){
      int b2=R0>>13, nloc=R0&8191;
      uint4 z={0,0,0,0};
      for(int i=tid;i<2048;i+=256){
        int c=i>>4, rr=(i&15)*8;
        int cs=(nt&1)*128+c;
        size_t base=((size_t)(b2*8+(cs>>5))*32+(cs&31))*8192+nloc+rr;
        *(uint4*)(g_vth+base)=z;
        *(uint4*)(g_vtl+base)=z;
      }
    }
    return;
  }
  uint32_t sbase=smem_u32(dsm);
  int wr=warp&3, wc=warp>>2;
  float acc[2][8][4];
  #pragma unroll
  for(int mt=0;mt<2;mt++)
    #pragma unroll
    for(int n2=0;n2<8;n2++)
      #pragma unroll
      for(int j=0;j<4;j++) acc[mt][n2][j]=0.f;
  auto issue=[&](int s){
    int st=s&1, k0=s*32;
    uint32_t so=sbase+st*40960u;
    #pragma unroll
    for(int j=0;j<2;j++){
      int i=tid+j*256;
      int r=i>>2, c=i&3;
      uint32_t off=(uint32_t)(r*80+c*16);
      cpa16(so+off,        g_xh+(size_t)(R0+r)*256+k0+c*8);
      cpa16(so+10240+off,  g_xl+(size_t)(R0+r)*256+k0+c*8);
      cpa16(so+20480+off,  g_wh+(size_t)(n0+r)*256+k0+c*8);
      cpa16(so+30720+off,  g_wl+(size_t)(n0+r)*256+k0+c*8);
    }
    cpa_commit();
  };
  auto compute=[&](int s){
    int st=s&1;
    uint32_t soA=sbase+st*40960u;
    uint32_t soAl=soA+10240u, soB=soA+20480u, soBl=soA+30720u;
    int rA=wr*32+(lane&15), rB=wc*64+(lane&15);
    #pragma unroll
    for(int kc=0;kc<2;kc++){
      int chi=kc*2+(lane>>4);
      uint32_t ah[2][4], al[2][4], bh[4][4], bl[4][4];
      #pragma unroll
      for(int mt=0;mt<2;mt++){
        uint32_t off=(uint32_t)((rA+mt*16)*80+chi*16);
        ldm4(ah[mt], soA+off); ldm4(al[mt], soAl+off);
      }
      #pragma unroll
      for(int nb=0;nb<4;nb++){
        uint32_t off=(uint32_t)((rB+nb*16)*80+chi*16);
        ldm4(bh[nb], soB+off); ldm4(bl[nb], soBl+off);
      }
      #pragma unroll
      for(int n2=0;n2<8;n2++){
        int nb=n2>>1, hi=n2&1;
        uint32_t b0h=bh[nb][hi], b1h=bh[nb][hi+2];
        uint32_t b0l=bl[nb][hi], b1l=bl[nb][hi+2];
        #pragma unroll
        for(int mt=0;mt<2;mt++){
          mma16816(acc[mt][n2], ah[mt], b0h, b1h);
          mma16816(acc[mt][n2], ah[mt], b0l, b1l);
          mma16816(acc[mt][n2], al[mt], b0h, b1h);
        }
      }
    }
  };
  issue(0); issue(1);
  for(int s=0;s<8;s++){
    if(s==7) cpa_wait<0>(); else cpa_wait<1>();
    __syncthreads();
    compute(s);
    __syncthreads();
    if(s<6) issue(s+2);
  }
  int g=lane>>2, t4=lane&3;
  const float* bias=(sec==0)?bq:((sec==1)?bk:bv);
  if(sec==2){
    int b2=R0>>13, nloc=R0&8191;
    #pragma unroll
    for(int n2=0;n2<8;n2++){
      int cs=(nt&1)*128+wc*64+n2*8+t4*2;
      float b0=bias[cs], b1=bias[cs+1];
      size_t ba0=((size_t)(b2*8+(cs>>5))*32+(cs&31))*8192+nloc;
      size_t ba1=ba0+8192;
      #pragma unroll
      for(int mt=0;mt<2;mt++){
        int r=wr*32+mt*16+g;
        float mk0=g_msk[R0+r]?1.f:0.f, mk1=g_msk[R0+r+8]?1.f:0.f;
        unsigned short h0,l0;
        f2hl((acc[mt][n2][0]+b0)*mk0,h0,l0); g_vth[ba0+r]=h0;   g_vtl[ba0+r]=l0;
        f2hl((acc[mt][n2][1]+b1)*mk0,h0,l0); g_vth[ba1+r]=h0;   g_vtl[ba1+r]=l0;
        f2hl((acc[mt][n2][2]+b0)*mk1,h0,l0); g_vth[ba0+r+8]=h0; g_vtl[ba0+r+8]=l0;
        f2hl((acc[mt][n2][3]+b1)*mk1,h0,l0); g_vth[ba1+r+8]=h0; g_vtl[ba1+r+8]=l0;
      }
    }
  }else{
    #pragma unroll
    for(int n2=0;n2<8;n2++){
      int cs=(nt&1)*128+wc*64+n2*8+t4*2;
      float b0=bias[cs], b1=bias[cs+1];
      #pragma unroll
      for(int mt=0;mt<2;mt++){
        int r=R0+wr*32+mt*16+g;
        unsigned short* Dh=sec?g_kh:g_qh;
        unsigned short* Dl=sec?g_kl:g_ql;
        unsigned short h0,l0,h1,l1;
        f2hl(acc[mt][n2][0]+b0,h0,l0); f2hl(acc[mt][n2][1]+b1,h1,l1);
        *(ushort2*)(Dh+(size_t)r*256+cs)=make_ushort2(h0,h1);
        *(ushort2*)(Dl+(size_t)r*256+cs)=make_ushort2(l0,l1);
        f2hl(acc[mt][n2][2]+b0,h0,l0); f2hl(acc[mt][n2][3]+b1,h1,l1);
        *(ushort2*)(Dh+(size_t)(r+8)*256+cs)=make_ushort2(h0,h1);
        *(ushort2*)(Dl+(size_t)(r+8)*256+cs)=make_ushort2(l0,l1);
      }
    }
  }
}

// ---- K3: kctx, register-repacked feature->ctx, cp.async ring-2 ----
// smem bytes: Ph 0..5120, Pl 5120..10240, stages at 10240+st*21760:
//   Kh +0, Kl +5120, VTh +10240 (40x144B), VTl +16000
#define KCTX_SMEM (53760)
__global__ void __launch_bounds__(256,2) k_kctx(){
  extern __shared__ __align__(128) char dsm[];
  unsigned short* PhS=(unsigned short*)dsm;
  unsigned short* PlS=PhS+2560;
  uint32_t sbase=smem_u32(dsm);
  uint32_t uPh=sbase, uPl=sbase+5120;
  int tid=threadIdx.x, lane=tid&31, warp=tid>>5;
  int b=blockIdx.z, h=blockIdx.y, chunk=blockIdx.x;
  int bh=b*HH+h;
  int wr=warp&3, wc=warp>>2;
  const float dn=0.42044820762685725f;
  { int m=tid>>2, c=(tid&3)*8;
    *(uint4*)(PhS+m*40+c)=*(const uint4*)(g_ph+m*32+c);
    *(uint4*)(PlS+m*40+c)=*(const uint4*)(g_pl+m*32+c);
  }
  // preset ones/zero rows 32..39 in both stages
  for(int st2=0;st2<2;st2++){
    unsigned short* VT0=(unsigned short*)(dsm+10240+st2*21760+10240);
    unsigned short* VT0l=(unsigned short*)(dsm+10240+st2*21760+16000);
    for(int i=tid;i<576;i+=256){
      VT0[2304+i]=(i<64)?0x3F80u:0u; VT0l[2304+i]=0u;
    }
  }
  int base=b*NN+chunk*512;
  size_t vhead=((size_t)bh*32)*8192;
  auto issue=[&](int s){
    int st=s&1, G=base+s*64, nloc=chunk*512+s*64;
    uint32_t sb=sbase+10240+st*21760;
    { int r=tid>>2, c=tid&3;
      uint32_t off=(uint32_t)(r*80+c*16);
      cpa16(sb+off,      g_kh+(size_t)(G+r)*256+h*32+c*8);
      cpa16(sb+5120+off, g_kl+(size_t)(G+r)*256+h*32+c*8);
    }
    { int d=tid>>3, c=tid&7;
      uint32_t off=(uint32_t)(d*144+c*16);
      size_t vb=vhead+(size_t)d*8192+nloc+c*8;
      cpa16(sb+10240+off, g_vth+vb);
      cpa16(sb+16000+off, g_vtl+vb);
    }
    cpa_commit();
  };
  float cacc[3][4];
  #pragma unroll
  for(int t=0;t<3;t++)
    #pragma unroll
    for(int j=0;j<4;j++) cacc[t][j]=0.f;
  __syncthreads();   // P + presets ready before compute; also before issue ok
  issue(0);
  int g2=lane>>2, t4=lane&3;
  // hoist P hi A-fragments
  uint32_t pa_h[2][4];
  { int rP=wr*16+(lane&15);
    #pragma unroll
    for(int kc=0;kc<2;kc++){
      int chi=kc*2+(lane>>4);
      ldm4(pa_h[kc], uPh+(uint32_t)(rP*80+chi*16));
    }
  }
  for(int s=0;s<8;s++){
    cpa_wait<0>();
    __syncthreads();
    if(s<7) issue(s+1);
    int st=s&1;
    uint32_t sb=sbase+10240+st*21760;
    uint32_t uKh=sb, uKl=sb+5120, uVh=sb+10240, uVl=sb+16000;
    // feature GEMM D[m][r]: A=P(m-tile wr), B=K rows (all 64)
    float fa[8][4];
    #pragma unroll
    for(int n2=0;n2<8;n2++)
      #pragma unroll
      for(int j=0;j<4;j++) fa[n2][j]=0.f;
    int rP=wr*16+(lane&15);
    #pragma unroll
    for(int kc=0;kc<2;kc++){
      int chi=kc*2+(lane>>4);
      uint32_t pl4[4];
      ldm4(pl4, uPl+(uint32_t)(rP*80+chi*16));
      uint32_t kb_h[4][4], kb_l[4][4];
      #pragma unroll
      for(int nb=0;nb<4;nb++){
        uint32_t off=(uint32_t)((nb*16+(lane&15))*80+chi*16);
        ldm4(kb_h[nb], uKh+off); ldm4(kb_l[nb], uKl+off);
      }
      #pragma unroll
      for(int n2=0;n2<8;n2++){
        int nb=n2>>1, hi=n2&1;
        uint32_t b0h=kb_h[nb][hi], b1h=kb_h[nb][hi+2];
        uint32_t b0l=kb_l[nb][hi], b1l=kb_l[nb][hi+2];
        mma16816(fa[n2], pa_h[kc], b0h, b1h);
        mma16816(fa[n2], pa_h[kc], b0l, b1l);
        mma16816(fa[n2], pl4,      b0h, b1h);
      }
    }
    // relu+eps + register repack -> A fragments for ctx GEMM
    uint32_t ca_h[4][4], ca_l[4][4];
    #pragma unroll
    for(int kc2=0;kc2<4;kc2++){
      #pragma unroll
      for(int half=0;half<2;half++){
        int n2=kc2*2+half;
        unsigned short h0,l0,h1,l1,h2,l2,h3,l3;
        f2hl(fmaxf(fa[n2][0]*dn,0.f)+1e-3f,h0,l0);
        f2hl(fmaxf(fa[n2][1]*dn,0.f)+1e-3f,h1,l1);
        f2hl(fmaxf(fa[n2][2]*dn,0.f)+1e-3f,h2,l2);
        f2hl(fmaxf(fa[n2][3]*dn,0.f)+1e-3f,h3,l3);
        ca_h[kc2][half*2]  =pk(h0,h1); ca_l[kc2][half*2]  =pk(l0,l1);
        ca_h[kc2][half*2+1]=pk(h2,h3); ca_l[kc2][half*2+1]=pk(l2,l3);
      }
    }
    // ctx GEMM: D[m][d'] accumulate, B=VT rows d'
    #pragma unroll
    for(int kc=0;kc<4;kc++){
      int chi=kc*2+(lane>>4);
      uint32_t b0h[4], b0l[4];
      if(wc==0){
        uint32_t o0=(uint32_t)((lane&15)*144+chi*16);
        uint32_t o1=(uint32_t)((16+(lane&15))*144+chi*16);
        uint32_t b1h[4], b1l[4];
        ldm4(b0h, uVh+o0); ldm4(b0l, uVl+o0);
        ldm4(b1h, uVh+o1); ldm4(b1l, uVl+o1);
        mma16816(cacc[0], ca_h[kc], b0h[0], b0h[2]); mma16816(cacc[0], ca_h[kc], b0l[0], b0l[2]); mma16816(cacc[0], ca_l[kc], b0h[0], b0h[2]);
        mma16816(cacc[1], ca_h[kc], b0h[1], b0h[3]); mma16816(cacc[1], ca_h[kc], b0l[1], b0l[3]); mma16816(cacc[1], ca_l[kc], b0h[1], b0h[3]);
        mma16816(cacc[2], ca_h[kc], b1h[0], b1h[2]); mma16816(cacc[2], ca_h[kc], b1l[0], b1l[2]); mma16816(cacc[2], ca_l[kc], b1h[0], b1h[2]);
      }else{
        uint32_t o0=(uint32_t)((24+(lane&15))*144+chi*16);
        ldm4(b0h, uVh+o0); ldm4(b0l, uVl+o0);
        mma16816(cacc[0], ca_h[kc], b0h[0], b0h[2]); mma16816(cacc[0], ca_h[kc], b0l[0], b0l[2]); mma16816(cacc[0], ca_l[kc], b0h[0], b0h[2]);
        mma16816(cacc[1], ca_h[kc], b0h[1], b0h[3]); mma16816(cacc[1], ca_h[kc], b0l[1], b0l[3]); mma16816(cacc[1], ca_l[kc], b0h[1], b0h[3]);
      }
    }
    __syncthreads();   // all reads of stage st done before its reuse
  }
  float* cp=g_ctx+((size_t)bh<<11);
  float* ks=g_ksum+bh*64;
  #pragma unroll
  for(int t=0;t<3;t++){
    if(wc==1 && t>=2) continue;
    int d0=(wc?24:0)+t*8+t4*2, m0=wr*16+g2;
    #pragma unroll
    for(int jj=0;jj<4;jj++){
      int m=m0+((jj>>1)<<3), d=d0+(jj&1);
      if(d<32) atomicAdd(cp+m*32+d, cacc[t][jj]);
      else if(d==32) atomicAdd(ks+m, cacc[t][jj]);
    }
  }
  // last block for this (b,h): convert ctx -> bf16 hi/lo transposed
  __shared__ int slast;
  __threadfence();
  if(tid==0) slast=atomicAdd(&g_cnt[bh],1);
  __syncthreads();
  if(slast==15){
    __threadfence();
    for(int i=tid;i<2048;i+=256){
      int d=i>>6, m=i&63;
      unsigned short hh,ll;
      f2hl(g_ctx[bh*2048+m*32+d],hh,ll);
      g_cth[bh*2048+i]=hh; g_ctl[bh*2048+i]=ll;
    }
  }
}

// ---- K4: qout, register-repacked qp->out, denom in registers ----
// smem shorts: Ph0 Pl2560 Qh5120 Ql7680 Ch10240(40x72) Cl13120 end 16000
#define QOUT_SMEM (32768)
__global__ void __launch_bounds__(256,2) k_qout(){
  extern __shared__ __align__(128) unsigned short sm[];
  unsigned short *Ph=sm, *Pl=sm+2560, *Qh=sm+5120, *Ql=sm+7680;
  unsigned short *Ch=sm+10240, *Cl=sm+13120;
  __shared__ float Ksm[64];
  __shared__ int anyv;
  uint32_t uPh=smem_u32(Ph), uPl=smem_u32(Pl), uQh=smem_u32(Qh), uQl=smem_u32(Ql);
  uint32_t uCh=smem_u32(Ch), uCl=smem_u32(Cl);
  int tid=threadIdx.x, lane=tid&31, warp=tid>>5;
  int tile=blockIdx.x, h=blockIdx.y;
  int G=tile*64, b=G>>13;
  int bh=b*HH+h;
  int wr=warp&3, wc=warp>>2;
  const float dn=0.42044820762685725f;
  if(tid==0) anyv=0;
  __syncthreads();
  if(tid<64 && g_msk[G+tid]) anyv=1;
  __syncthreads();
  if(!anyv) return;
  { int m=tid>>2, c=(tid&3)*8;
    *(uint4*)(Ph+m*40+c)=*(const uint4*)(g_ph+m*32+c);
    *(uint4*)(Pl+m*40+c)=*(const uint4*)(g_pl+m*32+c);
  }
  { int r=tid>>2, c=tid&3;
    *(uint4*)(Qh+r*40+c*8)=*(const uint4*)(g_qh+(size_t)(G+r)*256+h*32+c*8);
    *(uint4*)(Ql+r*40+c*8)=*(const uint4*)(g_ql+(size_t)(G+r)*256+h*32+c*8);
  }
  { int d=tid>>3, c=(tid&7)*8;
    *(uint4*)(Ch+d*72+c)=*(const uint4*)(g_cth+bh*2048+d*64+c);
    *(uint4*)(Cl+d*72+c)=*(const uint4*)(g_ctl+bh*2048+d*64+c);
  }
  if(tid<64) Ksm[tid]=g_ksum[bh*64+tid];
  __syncthreads();
  int g2=lane>>2, t4=lane&3;
  // qp GEMM D[r][m]: A=Q(r-tile wr), B=P all m
  float fa[8][4];
  #pragma unroll
  for(int n2=0;n2<8;n2++)
    #pragma unroll
    for(int j=0;j<4;j++) fa[n2][j]=0.f;
  int rQ=wr*16+(lane&15);
  #pragma unroll
  for(int kc=0;kc<2;kc++){
    int chi=kc*2+(lane>>4);
    uint32_t qa_h[4], qa_l[4];
    ldm4(qa_h, uQh+(uint32_t)(rQ*80+chi*16));
    ldm4(qa_l, uQl+(uint32_t)(rQ*80+chi*16));
    uint32_t pb_h[4][4], pb_l[4][4];
    #pragma unroll
    for(int nb=0;nb<4;nb++){
      uint32_t off=(uint32_t)((nb*16+(lane&15))*80+chi*16);
      ldm4(pb_h[nb], uPh+off); ldm4(pb_l[nb], uPl+off);
    }
    #pragma unroll
    for(int n2=0;n2<8;n2++){
      int nb=n2>>1, hi=n2&1;
      uint32_t b0h=pb_h[nb][hi], b1h=pb_h[nb][hi+2];
      uint32_t b0l=pb_l[nb][hi], b1l=pb_l[nb][hi+2];
      mma16816(fa[n2], qa_h, b0h, b1h);
      mma16816(fa[n2], qa_h, b0l, b1l);
      mma16816(fa[n2], qa_l, b0h, b1h);
    }
  }
  // relu+eps in fp32, denom partials, repack
  float p0=0.f, p1=0.f;
  uint32_t ca_h[4][4], ca_l[4][4];
  #pragma unroll
  for(int kc2=0;kc2<4;kc2++){
    #pragma unroll
    for(int half=0;half<2;half++){
      int n2=kc2*2+half;
      int m0=n2*8+t4*2;
      float v0=fmaxf(fa[n2][0]*dn,0.f)+1e-3f;
      float v1=fmaxf(fa[n2][1]*dn,0.f)+1e-3f;
      float v2=fmaxf(fa[n2][2]*dn,0.f)+1e-3f;
      float v3=fmaxf(fa[n2][3]*dn,0.f)+1e-3f;
      p0+=v0*Ksm[m0]+v1*Ksm[m0+1];
      p1+=v2*Ksm[m0]+v3*Ksm[m0+1];
      unsigned short h0,l0,h1,l1,h2,l2,h3,l3;
      f2hl(v0,h0,l0); f2hl(v1,h1,l1); f2hl(v2,h2,l2); f2hl(v3,h3,l3);
      ca_h[kc2][half*2]  =pk(h0,h1); ca_l[kc2][half*2]  =pk(l0,l1);
      ca_h[kc2][half*2+1]=pk(h2,h3); ca_l[kc2][half*2+1]=pk(l2,l3);
    }
  }
  p0+=__shfl_xor_sync(0xffffffffu,p0,1); p0+=__shfl_xor_sync(0xffffffffu,p0,2);
  p1+=__shfl_xor_sync(0xffffffffu,p1,1); p1+=__shfl_xor_sync(0xffffffffu,p1,2);
  float di0=1.f/p0, di1=1.f/p1;
  // out GEMM: D[r][d] = Qp · CtxT, B=Ch rows d (wc half)
  float oa[2][4];
  #pragma unroll
  for(int n2=0;n2<2;n2++)
    #pragma unroll
    for(int j=0;j<4;j++) oa[n2][j]=0.f;
  #pragma unroll
  for(int kc=0;kc<4;kc++){
    int chi=kc*2+(lane>>4);
    uint32_t off=(uint32_t)((wc*16+(lane&15))*144+chi*16);
    uint32_t cb_h[4], cb_l[4];
    ldm4(cb_h, uCh+off); ldm4(cb_l, uCl+off);
    #pragma unroll
    for(int n2=0;n2<2;n2++){
      mma16816(oa[n2], ca_h[kc], cb_h[n2], cb_h[n2+2]);
      mma16816(oa[n2], ca_h[kc], cb_l[n2], cb_l[n2+2]);
      mma16816(oa[n2], ca_l[kc], cb_h[n2], cb_h[n2+2]);
    }
  }
  #pragma unroll
  for(int n2=0;n2<2;n2++){
    int r=wr*16+g2, d=wc*16+n2*8+t4*2;
    unsigned short h0,l0,h1,l1;
    size_t base0=(size_t)(G+r)*256+h*32+d;
    size_t base1=(size_t)(G+r+8)*256+h*32+d;
    f2hl(oa[n2][0]*di0,h0,l0); f2hl(oa[n2][1]*di0,h1,l1);
    *(ushort2*)(g_ath+base0)=make_ushort2(h0,h1);
    *(ushort2*)(g_atl+base0)=make_ushort2(l0,l1);
    f2hl(oa[n2][2]*di1,h0,l0); f2hl(oa[n2][3]*di1,h1,l1);
    *(ushort2*)(g_ath+base1)=make_ushort2(h0,h1);
    *(ushort2*)(g_atl+base1)=make_ushort2(l0,l1);
  }
}

// ---- K5: Wo GEMM on mma + bias + residual + LN2 + pooling (unchanged) ----
#define WO_SMEM (102400)
__global__ void __launch_bounds__(256,2) k_wo_mma(
    const float* __restrict__ bo, const float* __restrict__ x,
    const float* __restrict__ g2, const float* __restrict__ b2){
  extern __shared__ __align__(128) char dsm[];
  __shared__ int anyv;
  int tid=threadIdx.x, lane=tid&31, warp=tid>>5;
  int R0=blockIdx.x*64;
  int b=R0>>13;
  if(tid==0) anyv=0;
  __syncthreads();
  if(tid<64 && g_msk[R0+tid]) anyv=1;
  __syncthreads();
  if(!anyv) return;
  uint32_t sbase=smem_u32(dsm);
  int wr=warp&1, wc=warp>>1;
  float acc[2][8][4];
  #pragma unroll
  for(int mt=0;mt<2;mt++)
    #pragma unroll
    for(int n2=0;n2<8;n2++)
      #pragma unroll
      for(int j=0;j<4;j++) acc[mt][n2][j]=0.f;
  auto issue=[&](int s){
    int st=s&1, k0=s*32;
    uint32_t so=sbase+st*51200u;
    { int r=tid>>2, c=tid&3;
      uint32_t off=(uint32_t)(r*80+c*16);
      cpa16(so+off,      g_ath+(size_t)(R0+r)*256+k0+c*8);
      cpa16(so+5120+off, g_atl+(size_t)(R0+r)*256+k0+c*8);
    }
    #pragma unroll
    for(int j=0;j<4;j++){
      int i=tid+j*256;
      int r=i>>2, c=i&3;
      uint32_t off=(uint32_t)(r*80+c*16);
      cpa16(so+10240+off, g_woh+(size_t)r*256+k0+c*8);
      cpa16(so+30720+off, g_wol+(size_t)r*256+k0+c*8);
    }
    cpa_commit();
  };
  auto compute=[&](int s){
    int st=s&1;
    uint32_t soA=sbase+st*51200u;
    uint32_t soAl=soA+5120u, soB=soA+10240u, soBl=soA+30720u;
    int rA=wr*32+(lane&15), rB=wc*64+(lane&15);
    #pragma unroll
    for(int kc=0;kc<2;kc++){
      int chi=kc*2+(lane>>4);
      uint32_t ah[2][4], al[2][4], bh[4][4], bl[4][4];
      #pragma unroll
      for(int mt=0;mt<2;mt++){
        uint32_t off=(uint32_t)((rA+mt*16)*80+chi*16);
        ldm4(ah[mt], soA+off); ldm4(al[mt], soAl+off);
      }
      #pragma unroll
      for(int nb=0;nb<4;nb++){
        uint32_t off=(uint32_t)((rB+nb*16)*80+chi*16);
        ldm4(bh[nb], soB+off); ldm4(bl[nb], soBl+off);
      }
      #pragma unroll
      for(int n2=0;n2<8;n2++){
        int nb=n2>>1, hi=n2&1;
        uint32_t b0h=bh[nb][hi], b1h=bh[nb][hi+2];
        uint32_t b0l=bl[nb][hi], b1l=bl[nb][hi+2];
        #pragma unroll
        for(int mt=0;mt<2;mt++){
          mma16816(acc[mt][n2], ah[mt], b0h, b1h);
          mma16816(acc[mt][n2], ah[mt], b0l, b1l);
          mma16816(acc[mt][n2], al[mt], b0h, b1h);
        }
      }
    }
  };
  issue(0); issue(1);
  for(int s=0;s<8;s++){
    if(s==7) cpa_wait<0>(); else cpa_wait<1>();
    __syncthreads();
    compute(s);
    __syncthreads();
    if(s<6) issue(s+2);
  }
  float* S=(float*)dsm;
  int g=lane>>2, t4=lane&3;
  #pragma unroll
  for(int n2=0;n2<8;n2++){
    int c=wc*64+n2*8+t4*2;
    float b0=bo[c], b1=bo[c+1];
    #pragma unroll
    for(int mt=0;mt<2;mt++){
      int r=wr*32+mt*16+g;
      S[r*260+c]      =acc[mt][n2][0]+b0+x[(size_t)(R0+r)*256+c];
      S[r*260+c+1]    =acc[mt][n2][1]+b1+x[(size_t)(R0+r)*256+c+1];
      S[(r+8)*260+c]  =acc[mt][n2][2]+b0+x[(size_t)(R0+r+8)*256+c];
      S[(r+8)*260+c+1]=acc[mt][n2][3]+b1+x[(size_t)(R0+r+8)*256+c+1];
    }
  }
  __syncthreads();
  #pragma unroll
  for(int i=0;i<8;i++){
    int r=warp*8+i;
    float s=0.f, sq=0.f;
    #pragma unroll
    for(int j=0;j<8;j++){
      float v=S[r*260+lane+32*j];
      s+=v; sq+=v*v;
    }
    #pragma unroll
    for(int o=16;o;o>>=1){
      s +=__shfl_xor_sync(0xffffffffu,s,o);
      sq+=__shfl_xor_sync(0xffffffffu,sq,o);
    }
    float mu=s*(1.f/256), var=sq*(1.f/256)-mu*mu;
    float rs=rsqrtf(var+1e-5f);
    #pragma unroll
    for(int j=0;j<8;j++){
      int c=lane+32*j;
      float v=S[r*260+c];
      S[r*260+c]=(v-mu)*rs*g2[c]+b2[c];
    }
  }
  __syncthreads();
  float mx=-3.402823466e38f, sm2=0.f;
  int got=0;
  for(int r=0;r<64;r++){
    if(g_msk[R0+r]){
      float v=S[r*260+tid];
      mx=fmaxf(mx,v); sm2+=v; got=1;
    }
  }
  if(got){
    atomicMax(&g_maxe[b*DD+tid], fenc(mx));
    atomicAdd(&g_sump[b*DD+tid], sm2);
  }
}

// ---- K6: finalize ----
__global__ void k_fin(float* __restrict__ out){
  __shared__ int cnt[256];
  int b=blockIdx.x, t=threadIdx.x;
  int c=0;
  for(int r=t;r<NN;r+=256) c+=g_msk[b*NN+r];
  cnt[t]=c; __syncthreads();
  for(int o=128;o;o>>=1){ if(t<o) cnt[t]+=cnt[t+o]; __syncthreads(); }
  int len=cnt[0]; if(len<1) len=1;
  out[b*256+t]=(fdec(g_maxe[b*256+t])+g_sump[b*256+t]/(float)len)*0.5f;
}

extern "C" void kernel_launch(void* const* d_in, const int* in_sizes, int n_in,
                              void* d_out, int out_size){
  const float* x   =(const float*)d_in[0];
  const void*  mp  = d_in[1];
  const float* g1  =(const float*)d_in[2];
  const float* b1  =(const float*)d_in[3];
  const float* Wq  =(const float*)d_in[4];
  const float* bq  =(const float*)d_in[5];
  const float* Wk  =(const float*)d_in[6];
  const float* bk  =(const float*)d_in[7];
  const float* Wv  =(const float*)d_in[8];
  const float* bv  =(const float*)d_in[9];
  const float* proj=(const float*)d_in[10];
  const float* Wo  =(const float*)d_in[11];
  const float* bo  =(const float*)d_in[12];
  const float* g2  =(const float*)d_in[13];
  const float* b2  =(const float*)d_in[14];

  cudaFuncSetAttribute(k_qkv_mma, cudaFuncAttributeMaxDynamicSharedMemorySize, QKV_SMEM3);
  cudaFuncSetAttribute(k_kctx,    cudaFuncAttributeMaxDynamicSharedMemorySize, KCTX_SMEM);
  cudaFuncSetAttribute(k_qout,    cudaFuncAttributeMaxDynamicSharedMemorySize, QOUT_SMEM);
  cudaFuncSetAttribute(k_wo_mma,  cudaFuncAttributeMaxDynamicSharedMemorySize, WO_SMEM);

  k_zero<<<1024,256>>>(Wq,Wk,Wv,Wo,proj,mp);
  k_ln1<<<ROWS/8,256>>>(x,g1,b1);
  k_qkv_mma<<<dim3(6,512),256,QKV_SMEM3>>>(bq,bk,bv);
  k_kctx<<<dim3(16,HH,BB),256,KCTX_SMEM>>>();        // profiled slot 4
  k_qout<<<dim3(ROWS/64,HH),256,QOUT_SMEM>>>();
  k_wo_mma<<<ROWS/64,256,WO_SMEM>>>(bo,x,g2,b2);
  k_fin<<<BB,256>>>((float*)d_out);
}

// round 15
// speedup vs baseline: 1.6413x; 1.6413x over previous
#include <cuda_runtime.h>
#include <cuda_bf16.h>
#include <cstdint>

#define BB 8
#define NN 8192
#define DD 256
#define HH 8
#define MM 64
#define ROWS (BB*NN)

__device__ __nv_bfloat16 g_xh[(size_t)ROWS*DD];
__device__ __nv_bfloat16 g_xl[(size_t)ROWS*DD];
__device__ __nv_bfloat16 g_wh[768*256];
__device__ __nv_bfloat16 g_wl[768*256];
__device__ __nv_bfloat16 g_woh[256*256];
__device__ __nv_bfloat16 g_wol[256*256];
__device__ unsigned short g_qh[(size_t)ROWS*DD];
__device__ unsigned short g_ql[(size_t)ROWS*DD];
__device__ unsigned short g_kh[(size_t)ROWS*DD];
__device__ unsigned short g_kl[(size_t)ROWS*DD];
__device__ unsigned short g_vth[(size_t)BB*HH*32*NN];
__device__ unsigned short g_vtl[(size_t)BB*HH*32*NN];
__device__ unsigned short g_ath[(size_t)ROWS*DD];
__device__ unsigned short g_atl[(size_t)ROWS*DD];
__device__ unsigned short g_ph[2048], g_pl[2048];
__device__ unsigned short g_cth[64*2048], g_ctl[64*2048];
__device__ float g_ctx[BB*HH*MM*32];
__device__ float g_ksum[BB*HH*MM];
__device__ unsigned char g_msk[ROWS];
__device__ unsigned int g_maxe[BB*DD];
__device__ float g_sump[BB*DD];

__device__ __forceinline__ unsigned int fenc(float f){
  unsigned int u=__float_as_uint(f);
  return (u&0x80000000u)?~u:(u|0x80000000u);
}
__device__ __forceinline__ float fdec(unsigned int u){
  unsigned int b=(u&0x80000000u)?(u&0x7fffffffu):~u;
  return __uint_as_float(b);
}
__device__ __forceinline__ void f2hl(float v, unsigned short&h, unsigned short&l){
  __nv_bfloat16 hb=__float2bfloat16(v);
  __nv_bfloat16 lb=__float2bfloat16(v-__bfloat162float(hb));
  h=*(unsigned short*)&hb; l=*(unsigned short*)&lb;
}
__device__ __forceinline__ float bfu(unsigned short u){
  __nv_bfloat16 h=*(__nv_bfloat16*)&u; return __bfloat162float(h);
}
__device__ __forceinline__ void mma16816(float* d, const uint32_t* a,
                                         uint32_t b0, uint32_t b1){
  asm volatile(
    "mma.sync.aligned.m16n8k16.row.col.f32.bf16.bf16.f32 "
    "{%0,%1,%2,%3}, {%4,%5,%6,%7}, {%8,%9}, {%0,%1,%2,%3};"
    : "+f"(d[0]),"+f"(d[1]),"+f"(d[2]),"+f"(d[3])
    : "r"(a[0]),"r"(a[1]),"r"(a[2]),"r"(a[3]),"r"(b0),"r"(b1));
}
__device__ __forceinline__ void ldm4(uint32_t* r, uint32_t addr){
  asm volatile("ldmatrix.sync.aligned.m8n8.x4.shared.b16 {%0,%1,%2,%3}, [%4];"
    : "=r"(r[0]),"=r"(r[1]),"=r"(r[2]),"=r"(r[3]) : "r"(addr));
}
__device__ __forceinline__ uint32_t smem_u32(const void* p){
  uint32_t a;
  asm("{ .reg .u64 t; cvta.to.shared.u64 t, %1; cvt.u32.u64 %0, t; }":"=r"(a):"l"(p));
  return a;
}
__device__ __forceinline__ void cpa16(uint32_t dst, const void* src){
  asm volatile("cp.async.cg.shared.global [%0], [%1], 16;"::"r"(dst),"l"(src):"memory");
}
__device__ __forceinline__ void cpa_commit(){
  asm volatile("cp.async.commit_group;":::"memory");
}
template<int N> __device__ __forceinline__ void cpa_wait(){
  asm volatile("cp.async.wait_group %0;"::"n"(N):"memory");
}

// ---- K0: zero + mask + weight/proj preps ----
__global__ void k_zero(const float* __restrict__ Wq, const float* __restrict__ Wk,
                       const float* __restrict__ Wv, const float* __restrict__ Wo,
                       const float* __restrict__ proj, const void* __restrict__ mp){
  int n=blockIdx.x, k=threadIdx.x;
  if(n<768){
    const float* W=(n<256)?Wq:((n<512)?Wk:Wv);
    float v=W[k*256+(n&255)];
    __nv_bfloat16 h=__float2bfloat16(v);
    g_wh[n*256+k]=h;
    g_wl[n*256+k]=__float2bfloat16(v-__bfloat162float(h));
  }else{
    int c=n-768;
    float v=Wo[k*256+c];
    __nv_bfloat16 h=__float2bfloat16(v);
    g_woh[c*256+k]=h;
    g_wol[c*256+k]=__float2bfloat16(v-__bfloat162float(h));
  }
  int i=n*256+k;
  if(n<8) f2hl(proj[i], g_ph[i], g_pl[i]);
  if(n<256){
    unsigned int w=*(const unsigned int*)mp;
    int v;
    if(w==0x3F800000u)      v=((const float*)mp)[i]!=0.f;
    else if(w==1u)          v=((const int*)mp)[i]!=0;
    else                    v=((const unsigned char*)mp)[i]!=0;
    g_msk[i]=(unsigned char)v;
  }
  if(i<BB*HH*MM*32) g_ctx[i]=0.f;
  if(i<BB*HH*MM)    g_ksum[i]=0.f;
  if(i<BB*DD){ g_maxe[i]=0u; g_sump[i]=0.f; }
}

// ---- K1: LayerNorm1 -> bf16 hi/lo ----
__global__ void __launch_bounds__(256) k_ln1(const float* __restrict__ x,
                                             const float* __restrict__ g,
                                             const float* __restrict__ b){
  int lane=threadIdx.x&31, w=threadIdx.x>>5;
  size_t row=(size_t)blockIdx.x*8+w;
  const float4* xr=(const float4*)(x+row*DD);
  float4 a0=xr[lane*2], a1=xr[lane*2+1];
  float s=a0.x+a0.y+a0.z+a0.w+a1.x+a1.y+a1.z+a1.w;
  #pragma unroll
  for(int o=16;o;o>>=1) s+=__shfl_xor_sync(0xffffffffu,s,o);
  float mu=s*(1.f/DD);
  float dv[8]={a0.x-mu,a0.y-mu,a0.z-mu,a0.w-mu,a1.x-mu,a1.y-mu,a1.z-mu,a1.w-mu};
  float q=0.f;
  #pragma unroll
  for(int j=0;j<8;j++) q+=dv[j]*dv[j];
  #pragma unroll
  for(int o=16;o;o>>=1) q+=__shfl_xor_sync(0xffffffffu,q,o);
  float rs=rsqrtf(q*(1.f/DD)+1e-5f);
  float4 g0=((const float4*)g)[lane*2], g1v=((const float4*)g)[lane*2+1];
  float4 b0=((const float4*)b)[lane*2], b1v=((const float4*)b)[lane*2+1];
  float gv[8]={g0.x,g0.y,g0.z,g0.w,g1v.x,g1v.y,g1v.z,g1v.w};
  float bvv[8]={b0.x,b0.y,b0.z,b0.w,b1v.x,b1v.y,b1v.z,b1v.w};
  uint4 hv, lv;
  unsigned short* hp=(unsigned short*)&hv;
  unsigned short* lp=(unsigned short*)&lv;
  #pragma unroll
  for(int j=0;j<8;j++) f2hl(dv[j]*rs*gv[j]+bvv[j], hp[j], lp[j]);
  *(uint4*)(g_xh+row*256+lane*8)=hv;
  *(uint4*)(g_xl+row*256+lane*8)=lv;
}

// ---- K2: QKV GEMM; q/k -> bf16 hi/lo, v -> transposed masked bf16 hi/lo ----
#define QKV_SMEM3 (81920)
__global__ void __launch_bounds__(256,2) k_qkv_mma(
    const float* __restrict__ bq, const float* __restrict__ bk,
    const float* __restrict__ bv){
  extern __shared__ __align__(128) char dsm[];
  __shared__ int anyv;
  int tid=threadIdx.x, lane=tid&31, warp=tid>>5;
  int nt=blockIdx.x, R0=blockIdx.y*128;
  int sec=nt>>1, n0=nt*128;
  if(tid==0) anyv=0;
  __syncthreads();
  if(tid<128 && g_msk[R0+tid]) anyv=1;
  __syncthreads();
  if(sec!=1 && !anyv){
    if(sec==2){
      int b2=R0>>13, nloc=R0&8191;
      uint4 z={0,0,0,0};
      for(int i=tid;i<2048;i+=256){
        int c=i>>4, rr=(i&15)*8;
        int cs=(nt&1)*128+c;
        size_t base=((size_t)(b2*8+(cs>>5))*32+(cs&31))*8192+nloc+rr;
        *(uint4*)(g_vth+base)=z;
        *(uint4*)(g_vtl+base)=z;
      }
    }
    return;
  }
  uint32_t sbase=smem_u32(dsm);
  int wr=warp&3, wc=warp>>2;
  float acc[2][8][4];
  #pragma unroll
  for(int mt=0;mt<2;mt++)
    #pragma unroll
    for(int n2=0;n2<8;n2++)
      #pragma unroll
      for(int j=0;j<4;j++) acc[mt][n2][j]=0.f;
  auto issue=[&](int s){
    int st=s&1, k0=s*32;
    uint32_t so=sbase+st*40960u;
    #pragma unroll
    for(int j=0;j<2;j++){
      int i=tid+j*256;
      int r=i>>2, c=i&3;
      uint32_t off=(uint32_t)(r*80+c*16);
      cpa16(so+off,        g_xh+(size_t)(R0+r)*256+k0+c*8);
      cpa16(so+10240+off,  g_xl+(size_t)(R0+r)*256+k0+c*8);
      cpa16(so+20480+off,  g_wh+(size_t)(n0+r)*256+k0+c*8);
      cpa16(so+30720+off,  g_wl+(size_t)(n0+r)*256+k0+c*8);
    }
    cpa_commit();
  };
  auto compute=[&](int s){
    int st=s&1;
    uint32_t soA=sbase+st*40960u;
    uint32_t soAl=soA+10240u, soB=soA+20480u, soBl=soA+30720u;
    int rA=wr*32+(lane&15), rB=wc*64+(lane&15);
    #pragma unroll
    for(int kc=0;kc<2;kc++){
      int chi=kc*2+(lane>>4);
      uint32_t ah[2][4], al[2][4], bh[4][4], bl[4][4];
      #pragma unroll
      for(int mt=0;mt<2;mt++){
        uint32_t off=(uint32_t)((rA+mt*16)*80+chi*16);
        ldm4(ah[mt], soA+off); ldm4(al[mt], soAl+off);
      }
      #pragma unroll
      for(int nb=0;nb<4;nb++){
        uint32_t off=(uint32_t)((rB+nb*16)*80+chi*16);
        ldm4(bh[nb], soB+off); ldm4(bl[nb], soBl+off);
      }
      #pragma unroll
      for(int n2=0;n2<8;n2++){
        int nb=n2>>1, hi=n2&1;
        uint32_t b0h=bh[nb][hi], b1h=bh[nb][hi+2];
        uint32_t b0l=bl[nb][hi], b1l=bl[nb][hi+2];
        #pragma unroll
        for(int mt=0;mt<2;mt++){
          mma16816(acc[mt][n2], ah[mt], b0h, b1h);
          mma16816(acc[mt][n2], ah[mt], b0l, b1l);
          mma16816(acc[mt][n2], al[mt], b0h, b1h);
        }
      }
    }
  };
  issue(0); issue(1);
  for(int s=0;s<8;s++){
    if(s==7) cpa_wait<0>(); else cpa_wait<1>();
    __syncthreads();
    compute(s);
    __syncthreads();
    if(s<6) issue(s+2);
  }
  int g=lane>>2, t4=lane&3;
  const float* bias=(sec==0)?bq:((sec==1)?bk:bv);
  if(sec==2){
    int b2=R0>>13, nloc=R0&8191;
    #pragma unroll
    for(int n2=0;n2<8;n2++){
      int cs=(nt&1)*128+wc*64+n2*8+t4*2;
      float b0=bias[cs], b1=bias[cs+1];
      size_t ba0=((size_t)(b2*8+(cs>>5))*32+(cs&31))*8192+nloc;
      size_t ba1=ba0+8192;
      #pragma unroll
      for(int mt=0;mt<2;mt++){
        int r=wr*32+mt*16+g;
        float mk0=g_msk[R0+r]?1.f:0.f, mk1=g_msk[R0+r+8]?1.f:0.f;
        unsigned short h0,l0;
        f2hl((acc[mt][n2][0]+b0)*mk0,h0,l0); g_vth[ba0+r]=h0;   g_vtl[ba0+r]=l0;
        f2hl((acc[mt][n2][1]+b1)*mk0,h0,l0); g_vth[ba1+r]=h0;   g_vtl[ba1+r]=l0;
        f2hl((acc[mt][n2][2]+b0)*mk1,h0,l0); g_vth[ba0+r+8]=h0; g_vtl[ba0+r+8]=l0;
        f2hl((acc[mt][n2][3]+b1)*mk1,h0,l0); g_vth[ba1+r+8]=h0; g_vtl[ba1+r+8]=l0;
      }
    }
  }else{
    #pragma unroll
    for(int n2=0;n2<8;n2++){
      int cs=(nt&1)*128+wc*64+n2*8+t4*2;
      float b0=bias[cs], b1=bias[cs+1];
      #pragma unroll
      for(int mt=0;mt<2;mt++){
        int r=R0+wr*32+mt*16+g;
        unsigned short* Dh=sec?g_kh:g_qh;
        unsigned short* Dl=sec?g_kl:g_ql;
        unsigned short h0,l0,h1,l1;
        f2hl(acc[mt][n2][0]+b0,h0,l0); f2hl(acc[mt][n2][1]+b1,h1,l1);
        *(ushort2*)(Dh+(size_t)r*256+cs)=make_ushort2(h0,h1);
        *(ushort2*)(Dl+(size_t)r*256+cs)=make_ushort2(l0,l1);
        f2hl(acc[mt][n2][2]+b0,h0,l0); f2hl(acc[mt][n2][3]+b1,h1,l1);
        *(ushort2*)(Dh+(size_t)(r+8)*256+cs)=make_ushort2(h0,h1);
        *(ushort2*)(Dl+(size_t)(r+8)*256+cs)=make_ushort2(l0,l1);
      }
    }
  }
}

// ---- K3: kctx (R11 structure) + cp.async ring-2 tile staging ----
// smem bytes: Ph 0, Pl 5120, Th 10240(9216), Tl 19456(9216),
// stages at 28672 + st*21760: Kh+0(5120) Kl+5120 VTh+10240(5760) VTl+16000(5760)
#define KCTX_SMEM (72192)
__global__ void __launch_bounds__(256,2) k_kctx(){
  extern __shared__ __align__(128) char dsm[];
  unsigned short* sm=(unsigned short*)dsm;
  unsigned short *Ph=sm, *Pl=sm+2560, *Th=sm+5120, *Tl=sm+9728;
  uint32_t sbase=smem_u32(dsm);
  uint32_t uPh=sbase, uPl=sbase+5120, uTh=sbase+10240, uTl=sbase+19456;
  int tid=threadIdx.x, lane=tid&31, warp=tid>>5;
  int b=blockIdx.z, h=blockIdx.y, chunk=blockIdx.x;
  int bh=b*HH+h;
  int wr=warp&3, wc=warp>>2;
  const float dn=0.42044820762685725f;
  { int m=tid>>2, c=(tid&3)*8;
    *(uint4*)(Ph+m*40+c)=*(const uint4*)(g_ph+m*32+c);
    *(uint4*)(Pl+m*40+c)=*(const uint4*)(g_pl+m*32+c);
  }
  // preset ones/zero rows 32..39 of VT in both stages
  for(int st2=0;st2<2;st2++){
    unsigned short* VTs=(unsigned short*)(dsm+28672+st2*21760+10240);
    unsigned short* VTsl=(unsigned short*)(dsm+28672+st2*21760+16000);
    for(int i=tid;i<576;i+=256){
      VTs[2304+i]=(i<64)?0x3F80u:0u; VTsl[2304+i]=0u;
    }
  }
  int base=b*NN+chunk*512;
  size_t vhead=((size_t)bh*32)*8192;
  auto issue=[&](int s){
    int st=s&1, G=base+s*64, nloc=chunk*512+s*64;
    uint32_t sb=sbase+28672+st*21760;
    { int r=tid>>2, c=tid&3;
      uint32_t off=(uint32_t)(r*80+c*16);
      cpa16(sb+off,      g_kh+(size_t)(G+r)*256+h*32+c*8);
      cpa16(sb+5120+off, g_kl+(size_t)(G+r)*256+h*32+c*8);
    }
    { int d=tid>>3, c=tid&7;
      uint32_t off=(uint32_t)(d*144+c*16);
      size_t vb=vhead+(size_t)d*8192+nloc+c*8;
      cpa16(sb+10240+off, g_vth+vb);
      cpa16(sb+16000+off, g_vtl+vb);
    }
    cpa_commit();
  };
  int ntile=(wc==0)?3:2;
  float cacc[3][4];
  #pragma unroll
  for(int t=0;t<3;t++)
    #pragma unroll
    for(int j=0;j<4;j++) cacc[t][j]=0.f;
  int g2=lane>>2, t4=lane&3;
  __syncthreads();          // P + presets visible
  issue(0); issue(1);
  for(int s=0;s<8;s++){
    if(s==7) cpa_wait<0>(); else cpa_wait<1>();
    __syncthreads();
    int st=s&1;
    uint32_t sb=sbase+28672+st*21760;
    uint32_t uKh=sb, uKl=sb+5120, uVh=sb+10240, uVl=sb+16000;
    // feature GEMM D[r][m]  (A=K rows, B=P)
    float fa[4][4];
    #pragma unroll
    for(int n2=0;n2<4;n2++)
      #pragma unroll
      for(int j=0;j<4;j++) fa[n2][j]=0.f;
    int rA=wr*16+(lane&15), rB=wc*32+(lane&15);
    #pragma unroll
    for(int kc=0;kc<2;kc++){
      int chi=kc*2+(lane>>4);
      uint32_t ah[4], al[4], bh2[2][4], bl2[2][4];
      ldm4(ah, uKh+(uint32_t)(rA*80+chi*16)); ldm4(al, uKl+(uint32_t)(rA*80+chi*16));
      #pragma unroll
      for(int nb=0;nb<2;nb++){
        uint32_t off=(uint32_t)((rB+nb*16)*80+chi*16);
        ldm4(bh2[nb], uPh+off); ldm4(bl2[nb], uPl+off);
      }
      #pragma unroll
      for(int n2=0;n2<4;n2++){
        int nb=n2>>1, hi=n2&1;
        mma16816(fa[n2], ah, bh2[nb][hi], bh2[nb][hi+2]);
        mma16816(fa[n2], ah, bl2[nb][hi], bl2[nb][hi+2]);
        mma16816(fa[n2], al, bh2[nb][hi], bh2[nb][hi+2]);
      }
    }
    #pragma unroll
    for(int n2=0;n2<4;n2++){
      int m=wc*32+n2*8+t4*2, r=wr*16+g2;
      float v0=fmaxf(fa[n2][0]*dn,0.f)+1e-3f;
      float v1=fmaxf(fa[n2][1]*dn,0.f)+1e-3f;
      float v2=fmaxf(fa[n2][2]*dn,0.f)+1e-3f;
      float v3=fmaxf(fa[n2][3]*dn,0.f)+1e-3f;
      f2hl(v0, Th[m*72+r],       Tl[m*72+r]);
      f2hl(v1, Th[(m+1)*72+r],   Tl[(m+1)*72+r]);
      f2hl(v2, Th[m*72+r+8],     Tl[m*72+r+8]);
      f2hl(v3, Th[(m+1)*72+r+8], Tl[(m+1)*72+r+8]);
    }
    __syncthreads();
    // ctx GEMM: D[m][d'] accumulate (d'=32 is ksum ones column)
    int rA2=wr*16+(lane&15);
    #pragma unroll
    for(int kc=0;kc<4;kc++){
      int chi=kc*2+(lane>>4);
      uint32_t ah[4], al[4], b0h[4], b0l[4];
      ldm4(ah, uTh+(uint32_t)(rA2*144+chi*16)); ldm4(al, uTl+(uint32_t)(rA2*144+chi*16));
      if(wc==0){
        uint32_t o0=(uint32_t)((lane&15)*144+chi*16);
        uint32_t o1=(uint32_t)((16+(lane&15))*144+chi*16);
        uint32_t b1h[4], b1l[4];
        ldm4(b0h, uVh+o0); ldm4(b0l, uVl+o0);
        ldm4(b1h, uVh+o1); ldm4(b1l, uVl+o1);
        mma16816(cacc[0], ah, b0h[0], b0h[2]); mma16816(cacc[0], ah, b0l[0], b0l[2]); mma16816(cacc[0], al, b0h[0], b0h[2]);
        mma16816(cacc[1], ah, b0h[1], b0h[3]); mma16816(cacc[1], ah, b0l[1], b0l[3]); mma16816(cacc[1], al, b0h[1], b0h[3]);
        mma16816(cacc[2], ah, b1h[0], b1h[2]); mma16816(cacc[2], ah, b1l[0], b1l[2]); mma16816(cacc[2], al, b1h[0], b1h[2]);
      }else{
        uint32_t o0=(uint32_t)((24+(lane&15))*144+chi*16);
        ldm4(b0h, uVh+o0); ldm4(b0l, uVl+o0);
        mma16816(cacc[0], ah, b0h[0], b0h[2]); mma16816(cacc[0], ah, b0l[0], b0l[2]); mma16816(cacc[0], al, b0h[0], b0h[2]);
        mma16816(cacc[1], ah, b0h[1], b0h[3]); mma16816(cacc[1], ah, b0l[1], b0l[3]); mma16816(cacc[1], al, b0h[1], b0h[3]);
      }
    }
    __syncthreads();      // stage st reads done before re-issue
    if(s<6) issue(s+2);
  }
  float* cp=g_ctx+((size_t)bh<<11);
  float* ks=g_ksum+bh*64;
  #pragma unroll
  for(int t=0;t<3;t++){
    if(t>=ntile) continue;
    int d0=(wc?24:0)+t*8+t4*2, m0=wr*16+g2;
    #pragma unroll
    for(int jj=0;jj<4;jj++){
      int m=m0+((jj>>1)<<3), d=d0+(jj&1);
      if(d<32) atomicAdd(cp+m*32+d, cacc[t][jj]);
      else if(d==32) atomicAdd(ks+m, cacc[t][jj]);
    }
  }
}

// ---- K3b: ctx -> bf16 hi/lo transposed [bh][d][m] ----
__global__ void k_ctxprep(){
  int bh=blockIdx.x, t=threadIdx.x;
  for(int i=t;i<2048;i+=256){
    int d=i>>6, m=i&63;
    unsigned short h,l;
    f2hl(g_ctx[bh*2048+m*32+d],h,l);
    g_cth[bh*2048+i]=h; g_ctl[bh*2048+i]=l;
  }
}

// ---- K4: qout (R11 version) ----
#define QOUT_SMEM (48128)
__global__ void __launch_bounds__(256) k_qout(){
  extern __shared__ __align__(128) unsigned short sm[];
  unsigned short *Ph=sm, *Pl=sm+2560, *Qh=sm+5120, *Ql=sm+7680;
  unsigned short *Sph=sm+10240, *Spl=sm+14848, *Ch=sm+19456, *Cl=sm+21760;
  __shared__ float Ksm[64], Dinv[64];
  __shared__ int anyv;
  uint32_t uPh=smem_u32(Ph), uPl=smem_u32(Pl), uQh=smem_u32(Qh), uQl=smem_u32(Ql);
  uint32_t uSh=smem_u32(Sph), uSl=smem_u32(Spl), uCh=smem_u32(Ch), uCl=smem_u32(Cl);
  int tid=threadIdx.x, lane=tid&31, warp=tid>>5;
  int tile=blockIdx.x, h=blockIdx.y;
  int G=tile*64, b=G>>13;
  int bh=b*HH+h;
  int wr=warp&3, wc=warp>>2;
  const float dn=0.42044820762685725f;
  if(tid==0) anyv=0;
  __syncthreads();
  if(tid<64 && g_msk[G+tid]) anyv=1;
  __syncthreads();
  if(!anyv) return;
  { int m=tid>>2, c=(tid&3)*8;
    *(uint4*)(Ph+m*40+c)=*(const uint4*)(g_ph+m*32+c);
    *(uint4*)(Pl+m*40+c)=*(const uint4*)(g_pl+m*32+c);
  }
  { int r=tid>>2, c=tid&3;
    *(uint4*)(Qh+r*40+c*8)=*(const uint4*)(g_qh+(size_t)(G+r)*256+h*32+c*8);
    *(uint4*)(Ql+r*40+c*8)=*(const uint4*)(g_ql+(size_t)(G+r)*256+h*32+c*8);
  }
  { int d=tid>>3, c=(tid&7)*8;
    *(uint4*)(Ch+d*72+c)=*(const uint4*)(g_cth+bh*2048+d*64+c);
    *(uint4*)(Cl+d*72+c)=*(const uint4*)(g_ctl+bh*2048+d*64+c);
  }
  if(tid<64) Ksm[tid]=g_ksum[bh*64+tid];
  __syncthreads();
  {
    float fa[4][4];
    #pragma unroll
    for(int n2=0;n2<4;n2++)
      #pragma unroll
      for(int j=0;j<4;j++) fa[n2][j]=0.f;
    int rA=wr*16+(lane&15), rB=wc*32+(lane&15);
    #pragma unroll
    for(int kc=0;kc<2;kc++){
      int chi=kc*2+(lane>>4);
      uint32_t ah[4], al[4], bh2[2][4], bl2[2][4];
      ldm4(ah, uQh+(uint32_t)(rA*80+chi*16)); ldm4(al, uQl+(uint32_t)(rA*80+chi*16));
      #pragma unroll
      for(int nb=0;nb<2;nb++){
        uint32_t off=(uint32_t)((rB+nb*16)*80+chi*16);
        ldm4(bh2[nb], uPh+off); ldm4(bl2[nb], uPl+off);
      }
      #pragma unroll
      for(int n2=0;n2<4;n2++){
        int nb=n2>>1, hi=n2&1;
        mma16816(fa[n2], ah, bh2[nb][hi], bh2[nb][hi+2]);
        mma16816(fa[n2], ah, bl2[nb][hi], bl2[nb][hi+2]);
        mma16816(fa[n2], al, bh2[nb][hi], bh2[nb][hi+2]);
      }
    }
    int g2=lane>>2, t4=lane&3;
    #pragma unroll
    for(int n2=0;n2<4;n2++){
      int m=wc*32+n2*8+t4*2, r=wr*16+g2;
      float v0=fmaxf(fa[n2][0]*dn,0.f)+1e-3f;
      float v1=fmaxf(fa[n2][1]*dn,0.f)+1e-3f;
      float v2=fmaxf(fa[n2][2]*dn,0.f)+1e-3f;
      float v3=fmaxf(fa[n2][3]*dn,0.f)+1e-3f;
      f2hl(v0, Sph[r*72+m],       Spl[r*72+m]);
      f2hl(v1, Sph[r*72+m+1],     Spl[r*72+m+1]);
      f2hl(v2, Sph[(r+8)*72+m],   Spl[(r+8)*72+m]);
      f2hl(v3, Sph[(r+8)*72+m+1], Spl[(r+8)*72+m+1]);
    }
  }
  __syncthreads();
  if(tid<64){
    float s=0.f;
    #pragma unroll 8
    for(int m=0;m<64;m++)
      s+=(bfu(Sph[tid*72+m])+bfu(Spl[tid*72+m]))*Ksm[m];
    Dinv[tid]=1.f/s;
  }
  __syncthreads();
  {
    float oa[2][4];
    #pragma unroll
    for(int n2=0;n2<2;n2++)
      #pragma unroll
      for(int j=0;j<4;j++) oa[n2][j]=0.f;
    int rA=wr*16+(lane&15), rB=wc*16+(lane&15);
    #pragma unroll
    for(int kc=0;kc<4;kc++){
      int chi=kc*2+(lane>>4);
      uint32_t ah[4], al[4], bh2[4], bl2[4];
      ldm4(ah, uSh+(uint32_t)(rA*144+chi*16)); ldm4(al, uSl+(uint32_t)(rA*144+chi*16));
      ldm4(bh2, uCh+(uint32_t)(rB*144+chi*16)); ldm4(bl2, uCl+(uint32_t)(rB*144+chi*16));
      #pragma unroll
      for(int n2=0;n2<2;n2++){
        mma16816(oa[n2], ah, bh2[n2], bh2[n2+2]);
        mma16816(oa[n2], ah, bl2[n2], bl2[n2+2]);
        mma16816(oa[n2], al, bh2[n2], bh2[n2+2]);
      }
    }
    int g2=lane>>2, t4=lane&3;
    #pragma unroll
    for(int n2=0;n2<2;n2++){
      int r=wr*16+g2, d=wc*16+n2*8+t4*2;
      float di0=Dinv[r], di1=Dinv[r+8];
      unsigned short h0,l0,h1,l1;
      size_t base0=(size_t)(G+r)*256+h*32+d;
      size_t base1=(size_t)(G+r+8)*256+h*32+d;
      f2hl(oa[n2][0]*di0,h0,l0); f2hl(oa[n2][1]*di0,h1,l1);
      *(ushort2*)(g_ath+base0)=make_ushort2(h0,h1);
      *(ushort2*)(g_atl+base0)=make_ushort2(l0,l1);
      f2hl(oa[n2][2]*di1,h0,l0); f2hl(oa[n2][3]*di1,h1,l1);
      *(ushort2*)(g_ath+base1)=make_ushort2(h0,h1);
      *(ushort2*)(g_atl+base1)=make_ushort2(l0,l1);
    }
  }
}

// ---- K5: Wo GEMM on mma + bias + residual + LN2 + pooling ----
#define WO_SMEM (102400)
__global__ void __launch_bounds__(256,2) k_wo_mma(
    const float* __restrict__ bo, const float* __restrict__ x,
    const float* __restrict__ g2, const float* __restrict__ b2){
  extern __shared__ __align__(128) char dsm[];
  __shared__ int anyv;
  int tid=threadIdx.x, lane=tid&31, warp=tid>>5;
  int R0=blockIdx.x*64;
  int b=R0>>13;
  if(tid==0) anyv=0;
  __syncthreads();
  if(tid<64 && g_msk[R0+tid]) anyv=1;
  __syncthreads();
  if(!anyv) return;
  uint32_t sbase=smem_u32(dsm);
  int wr=warp&1, wc=warp>>1;
  float acc[2][8][4];
  #pragma unroll
  for(int mt=0;mt<2;mt++)
    #pragma unroll
    for(int n2=0;n2<8;n2++)
      #pragma unroll
      for(int j=0;j<4;j++) acc[mt][n2][j]=0.f;
  auto issue=[&](int s){
    int st=s&1, k0=s*32;
    uint32_t so=sbase+st*51200u;
    { int r=tid>>2, c=tid&3;
      uint32_t off=(uint32_t)(r*80+c*16);
      cpa16(so+off,      g_ath+(size_t)(R0+r)*256+k0+c*8);
      cpa16(so+5120+off, g_atl+(size_t)(R0+r)*256+k0+c*8);
    }
    #pragma unroll
    for(int j=0;j<4;j++){
      int i=tid+j*256;
      int r=i>>2, c=i&3;
      uint32_t off=(uint32_t)(r*80+c*16);
      cpa16(so+10240+off, g_woh+(size_t)r*256+k0+c*8);
      cpa16(so+30720+off, g_wol+(size_t)r*256+k0+c*8);
    }
    cpa_commit();
  };
  auto compute=[&](int s){
    int st=s&1;
    uint32_t soA=sbase+st*51200u;
    uint32_t soAl=soA+5120u, soB=soA+10240u, soBl=soA+30720u;
    int rA=wr*32+(lane&15), rB=wc*64+(lane&15);
    #pragma unroll
    for(int kc=0;kc<2;kc++){
      int chi=kc*2+(lane>>4);
      uint32_t ah[2][4], al[2][4], bh[4][4], bl[4][4];
      #pragma unroll
      for(int mt=0;mt<2;mt++){
        uint32_t off=(uint32_t)((rA+mt*16)*80+chi*16);
        ldm4(ah[mt], soA+off); ldm4(al[mt], soAl+off);
      }
      #pragma unroll
      for(int nb=0;nb<4;nb++){
        uint32_t off=(uint32_t)((rB+nb*16)*80+chi*16);
        ldm4(bh[nb], soB+off); ldm4(bl[nb], soBl+off);
      }
      #pragma unroll
      for(int n2=0;n2<8;n2++){
        int nb=n2>>1, hi=n2&1;
        uint32_t b0h=bh[nb][hi], b1h=bh[nb][hi+2];
        uint32_t b0l=bl[nb][hi], b1l=bl[nb][hi+2];
        #pragma unroll
        for(int mt=0;mt<2;mt++){
          mma16816(acc[mt][n2], ah[mt], b0h, b1h);
          mma16816(acc[mt][n2], ah[mt], b0l, b1l);
          mma16816(acc[mt][n2], al[mt], b0h, b1h);
        }
      }
    }
  };
  issue(0); issue(1);
  for(int s=0;s<8;s++){
    if(s==7) cpa_wait<0>(); else cpa_wait<1>();
    __syncthreads();
    compute(s);
    __syncthreads();
    if(s<6) issue(s+2);
  }
  float* S=(float*)dsm;
  int g=lane>>2, t4=lane&3;
  #pragma unroll
  for(int n2=0;n2<8;n2++){
    int c=wc*64+n2*8+t4*2;
    float b0=bo[c], b1=bo[c+1];
    #pragma unroll
    for(int mt=0;mt<2;mt++){
      int r=wr*32+mt*16+g;
      S[r*260+c]      =acc[mt][n2][0]+b0+x[(size_t)(R0+r)*256+c];
      S[r*260+c+1]    =acc[mt][n2][1]+b1+x[(size_t)(R0+r)*256+c+1];
      S[(r+8)*260+c]  =acc[mt][n2][2]+b0+x[(size_t)(R0+r+8)*256+c];
      S[(r+8)*260+c+1]=acc[mt][n2][3]+b1+x[(size_t)(R0+r+8)*256+c+1];
    }
  }
  __syncthreads();
  #pragma unroll
  for(int i=0;i<8;i++){
    int r=warp*8+i;
    float s=0.f, sq=0.f;
    #pragma unroll
    for(int j=0;j<8;j++){
      float v=S[r*260+lane+32*j];
      s+=v; sq+=v*v;
    }
    #pragma unroll
    for(int o=16;o;o>>=1){
      s +=__shfl_xor_sync(0xffffffffu,s,o);
      sq+=__shfl_xor_sync(0xffffffffu,sq,o);
    }
    float mu=s*(1.f/256), var=sq*(1.f/256)-mu*mu;
    float rs=rsqrtf(var+1e-5f);
    #pragma unroll
    for(int j=0;j<8;j++){
      int c=lane+32*j;
      float v=S[r*260+c];
      S[r*260+c]=(v-mu)*rs*g2[c]+b2[c];
    }
  }
  __syncthreads();
  float mx=-3.402823466e38f, sm2=0.f;
  int got=0;
  for(int r=0;r<64;r++){
    if(g_msk[R0+r]){
      float v=S[r*260+tid];
      mx=fmaxf(mx,v); sm2+=v; got=1;
    }
  }
  if(got){
    atomicMax(&g_maxe[b*DD+tid], fenc(mx));
    atomicAdd(&g_sump[b*DD+tid], sm2);
  }
}

// ---- K6: finalize ----
__global__ void k_fin(float* __restrict__ out){
  __shared__ int cnt[256];
  int b=blockIdx.x, t=threadIdx.x;
  int c=0;
  for(int r=t;r<NN;r+=256) c+=g_msk[b*NN+r];
  cnt[t]=c; __syncthreads();
  for(int o=128;o;o>>=1){ if(t<o) cnt[t]+=cnt[t+o]; __syncthreads(); }
  int len=cnt[0]; if(len<1) len=1;
  out[b*256+t]=(fdec(g_maxe[b*256+t])+g_sump[b*256+t]/(float)len)*0.5f;
}

extern "C" void kernel_launch(void* const* d_in, const int* in_sizes, int n_in,
                              void* d_out, int out_size){
  const float* x   =(const float*)d_in[0];
  const void*  mp  = d_in[1];
  const float* g1  =(const float*)d_in[2];
  const float* b1  =(const float*)d_in[3];
  const float* Wq  =(const float*)d_in[4];
  const float* bq  =(const float*)d_in[5];
  const float* Wk  =(const float*)d_in[6];
  const float* bk  =(const float*)d_in[7];
  const float* Wv  =(const float*)d_in[8];
  const float* bv  =(const float*)d_in[9];
  const float* proj=(const float*)d_in[10];
  const float* Wo  =(const float*)d_in[11];
  const float* bo  =(const float*)d_in[12];
  const float* g2  =(const float*)d_in[13];
  const float* b2  =(const float*)d_in[14];

  cudaFuncSetAttribute(k_qkv_mma, cudaFuncAttributeMaxDynamicSharedMemorySize, QKV_SMEM3);
  cudaFuncSetAttribute(k_kctx,    cudaFuncAttributeMaxDynamicSharedMemorySize, KCTX_SMEM);
  cudaFuncSetAttribute(k_qout,    cudaFuncAttributeMaxDynamicSharedMemorySize, QOUT_SMEM);
  cudaFuncSetAttribute(k_wo_mma,  cudaFuncAttributeMaxDynamicSharedMemorySize, WO_SMEM);

  k_zero<<<1024,256>>>(Wq,Wk,Wv,Wo,proj,mp);
  k_ln1<<<ROWS/8,256>>>(x,g1,b1);
  k_qkv_mma<<<dim3(6,512),256,QKV_SMEM3>>>(bq,bk,bv);
  k_kctx<<<dim3(16,HH,BB),256,KCTX_SMEM>>>();        // profiled slot 4
  k_ctxprep<<<64,256>>>();
  k_qout<<<dim3(ROWS/64,HH),256,QOUT_SMEM>>>();
  k_wo_mma<<<ROWS/64,256,WO_SMEM>>>(bo,x,g2,b2);
  k_fin<<<BB,256>>>((float*)d_out);
}